// round 15
// baseline (speedup 1.0000x reference)
#include <cuda_runtime.h>
#include <cuda_bf16.h>

// Problem: B=64, L=1024, D=1280
//   pool_len = lengths + 2
//   emb[b,d]  = mean over l < pool_len of prev[b,l,d]
//   x         = relu(emb @ dense_w + dense_b)        [64,1280]
//   out       = x @ cls_w + cls_b                    [64,1]
//
// Two launches:
//  1) pool_kernel : 592 blocks x 320 thr (R11 config, measured 36.7us — best
//     of all pool variants tried). Exact task list over valid 64-row segments;
//     last-arriving block per b reduces partials, writes embT[k][b].
//  2) epilogue_kernel : 160 blocks x 128 thr, all co-resident.
//     Phase G: KS=16 k-split GEMM, block tile 64b x 128j x 80k, thread tile
//     8b x 8j (1.0 B LDS per FMA -> FMA-bound). Grid barrier. Phase F:
//     k-reduce + bias + relu + cls dot, atomicAdd into out.

#define Bq     64
#define Lq     1024
#define Dq     1280
#define D4     320           // float4 per row
#define SEGR   64            // rows per pool segment
#define MAXSEG 16
#define GPOOL  592           // pool blocks

#define KS     16            // GEMM k-splits
#define KCH    80            // k per split
#define KC     40            // k per smem stage
#define NJ     10            // j tiles
#define JTW    128           // j tile width
#define NEPI   160           // epilogue blocks (co-resident: <= 148*2)

typedef unsigned long long u64;

// scratch (allocation-free: __device__ globals)
__device__ float    g_part [Bq * MAXSEG * Dq];  // pool partials (5.24 MB)
__device__ float    g_embT [Dq * Bq];           // emb transposed [k][b]
__device__ float    g_xpart[KS * Bq * Dq];      // GEMM k-partials (5.24 MB)
__device__ unsigned g_cnt  [Bq];                // pool arrival counters

// epilogue grid-barrier state (count returns to 0; phase grows monotonically
// -> replay-safe without reinitialization)
__device__ unsigned g_bar_count = 0;
__device__ unsigned g_bar_phase = 0;

// packed f32x2 FMA (SASS FFMA2)
__device__ __forceinline__ u64 ffma2(u64 a, u64 b, u64 c) {
    u64 d;
    asm("fma.rn.f32x2 %0, %1, %2, %3;" : "=l"(d) : "l"(a), "l"(b), "l"(c));
    return d;
}
__device__ __forceinline__ u64 pack2(float lo, float hi) {
    u64 d;
    asm("mov.b64 %0, {%1, %2};" : "=l"(d) : "f"(lo), "f"(hi));
    return d;
}
__device__ __forceinline__ void unpack2(u64 v, float& lo, float& hi) {
    asm("mov.b64 {%0, %1}, %2;" : "=f"(lo), "=f"(hi) : "l"(v));
}

// ---------------------------------------------------------------------------
// Kernel 1: balanced ragged pool + fused per-b reduction (R11 config, proven).
// ---------------------------------------------------------------------------
__global__ void __launch_bounds__(D4) pool_kernel(
    const float* __restrict__ prev, const int* __restrict__ lengths)
{
    __shared__ int s_pre[Bq + 1];
    __shared__ int s_last;

    const int tid = threadIdx.x;
    const int bid = blockIdx.x;

    if (tid == 0) {
        int acc = 0;
        s_pre[0] = 0;
        for (int b = 0; b < Bq; ++b) {
            int pl = lengths[b] + 2;
            acc += (pl + SEGR - 1) >> 6;          // ceil(pl/64)
            s_pre[b + 1] = acc;
        }
    }
    __syncthreads();
    const int S = s_pre[Bq];                      // total valid segments

    for (int t = bid; t < S; t += GPOOL) {
        // binary search: b with s_pre[b] <= t < s_pre[b+1]
        int lo = 0, hi = Bq;
        while (hi - lo > 1) {
            int m = (lo + hi) >> 1;
            if (s_pre[m] <= t) lo = m; else hi = m;
        }
        const int b    = lo;
        const int seg  = t - s_pre[b];
        const int pl   = lengths[b] + 2;
        const int l0   = seg * SEGR;
        const int n    = min(SEGR, pl - l0);      // >= 1 by construction
        const int nseg = s_pre[b + 1] - s_pre[b];

        float4 a0 = make_float4(0.f, 0.f, 0.f, 0.f);
        float4 a1 = a0, a2 = a0, a3 = a0;

        const float4* __restrict__ p =
            reinterpret_cast<const float4*>(prev) + ((size_t)b * Lq + l0) * D4 + tid;
        int l = 0;
        for (; l + 8 <= n; l += 8) {
            float4 v0 = p[(size_t)(l + 0) * D4];
            float4 v1 = p[(size_t)(l + 1) * D4];
            float4 v2 = p[(size_t)(l + 2) * D4];
            float4 v3 = p[(size_t)(l + 3) * D4];
            float4 v4 = p[(size_t)(l + 4) * D4];
            float4 v5 = p[(size_t)(l + 5) * D4];
            float4 v6 = p[(size_t)(l + 6) * D4];
            float4 v7 = p[(size_t)(l + 7) * D4];
            a0.x += v0.x; a0.y += v0.y; a0.z += v0.z; a0.w += v0.w;
            a1.x += v1.x; a1.y += v1.y; a1.z += v1.z; a1.w += v1.w;
            a2.x += v2.x; a2.y += v2.y; a2.z += v2.z; a2.w += v2.w;
            a3.x += v3.x; a3.y += v3.y; a3.z += v3.z; a3.w += v3.w;
            a0.x += v4.x; a0.y += v4.y; a0.z += v4.z; a0.w += v4.w;
            a1.x += v5.x; a1.y += v5.y; a1.z += v5.z; a1.w += v5.w;
            a2.x += v6.x; a2.y += v6.y; a2.z += v6.z; a2.w += v6.w;
            a3.x += v7.x; a3.y += v7.y; a3.z += v7.z; a3.w += v7.w;
        }
        for (; l < n; ++l) {
            float4 v = p[(size_t)l * D4];
            a0.x += v.x; a0.y += v.y; a0.z += v.z; a0.w += v.w;
        }
        float4 s;
        s.x = (a0.x + a1.x) + (a2.x + a3.x);
        s.y = (a0.y + a1.y) + (a2.y + a3.y);
        s.z = (a0.z + a1.z) + (a2.z + a3.z);
        s.w = (a0.w + a1.w) + (a2.w + a3.w);
        reinterpret_cast<float4*>(g_part)[((size_t)b * MAXSEG + seg) * D4 + tid] = s;

        // publish partial, count arrival; last arrival reduces this b
        __threadfence();
        __syncthreads();
        if (tid == 0) {
            unsigned old = atomicAdd(&g_cnt[b], 1u);
            s_last = (((old + 1u) % (unsigned)nseg) == 0u) ? 1 : 0;
        }
        __syncthreads();
        if (s_last) {
            __threadfence();   // acquire other blocks' partials
            const float4* gp = reinterpret_cast<const float4*>(g_part)
                               + (size_t)b * MAXSEG * D4 + tid;
            float4 r = make_float4(0.f, 0.f, 0.f, 0.f);
            for (int sg = 0; sg < nseg; ++sg) {
                float4 v = gp[(size_t)sg * D4];
                r.x += v.x; r.y += v.y; r.z += v.z; r.w += v.w;
            }
            const float inv = 1.0f / (float)pl;
            r.x *= inv; r.y *= inv; r.z *= inv; r.w *= inv;
            g_embT[(size_t)(4 * tid + 0) * Bq + b] = r.x;
            g_embT[(size_t)(4 * tid + 1) * Bq + b] = r.y;
            g_embT[(size_t)(4 * tid + 2) * Bq + b] = r.z;
            g_embT[(size_t)(4 * tid + 3) * Bq + b] = r.w;
        }
        __syncthreads();       // protect s_last across task iterations
    }
}

// ---------------------------------------------------------------------------
// Kernel 2: fused GEMM + final. 160 blocks x 128 thr, all co-resident.
// ---------------------------------------------------------------------------
__global__ void __launch_bounds__(128) epilogue_kernel(
    const float* __restrict__ W,
    const float* __restrict__ dense_b,
    const float* __restrict__ cls_w,
    const float* __restrict__ cls_b,
    float*       __restrict__ out)
{
    __shared__ __align__(16) float4 sE4[KC][Bq / 4];   // embT stage 10 KB
    __shared__ __align__(16) float4 sW4[KC][JTW / 4];  // W stage    20 KB

    const int bid = blockIdx.x;
    const int tid = threadIdx.x;

    // ---- Phase G: k-split GEMM, thread tile 8b x 8j ----
    {
        const int ky = bid / NJ;                  // 0..15
        const int jx = bid % NJ;                  // 0..9
        const int k0 = ky * KCH;
        const int j0 = jx * JTW;
        const int bq = tid >> 4;                  // 0..7 -> b = 8bq..8bq+7
        const int jg = tid & 15;                  // 0..15 -> j = 8jg..8jg+7

        if (bid == 0 && tid < Bq)                 // init out for phase F atomics
            out[tid] = cls_b[0];

        u64 acc[8][4];
#pragma unroll
        for (int bi = 0; bi < 8; ++bi)
#pragma unroll
            for (int jp = 0; jp < 4; ++jp) acc[bi][jp] = 0ull;

        const float4* embT4 = reinterpret_cast<const float4*>(g_embT);
        const float4* W4    = reinterpret_cast<const float4*>(W);

        for (int c = 0; c < KCH; c += KC) {
            __syncthreads();
            // stage embT chunk: 40 rows x 16 float4
            for (int i = tid; i < KC * 16; i += 128) {
                int kk = i >> 4;
                int b4 = i & 15;
                sE4[kk][b4] = embT4[(size_t)(k0 + c + kk) * 16 + b4];
            }
            // stage W tile: 40 rows x 32 float4
            for (int i = tid; i < KC * 32; i += 128) {
                int kk = i >> 5;
                int j4 = i & 31;
                sW4[kk][j4] = W4[(size_t)(k0 + c + kk) * (Dq / 4) + (j0 / 4) + j4];
            }
            __syncthreads();

#pragma unroll 4
            for (int kk = 0; kk < KC; ++kk) {
                float4 e0 = sE4[kk][2 * bq];
                float4 e1 = sE4[kk][2 * bq + 1];
                float4 w0 = sW4[kk][2 * jg];
                float4 w1 = sW4[kk][2 * jg + 1];
                u64 wp[4];
                wp[0] = pack2(w0.x, w0.y); wp[1] = pack2(w0.z, w0.w);
                wp[2] = pack2(w1.x, w1.y); wp[3] = pack2(w1.z, w1.w);
                float eb[8] = {e0.x, e0.y, e0.z, e0.w, e1.x, e1.y, e1.z, e1.w};
#pragma unroll
                for (int bi = 0; bi < 8; ++bi) {
                    u64 ed = pack2(eb[bi], eb[bi]);
#pragma unroll
                    for (int jp = 0; jp < 4; ++jp)
                        acc[bi][jp] = ffma2(ed, wp[jp], acc[bi][jp]);
                }
            }
        }

        // store 8 rows x 8 j
        const int b0 = 8 * bq;
#pragma unroll
        for (int bi = 0; bi < 8; ++bi) {
            float x0, y0, z0, w0f, x1, y1, z1, w1f;
            unpack2(acc[bi][0], x0, y0);
            unpack2(acc[bi][1], z0, w0f);
            unpack2(acc[bi][2], x1, y1);
            unpack2(acc[bi][3], z1, w1f);
            float* dst = &g_xpart[((size_t)ky * Bq + b0 + bi) * Dq + j0 + 8 * jg];
            reinterpret_cast<float4*>(dst)[0] = make_float4(x0, y0, z0, w0f);
            reinterpret_cast<float4*>(dst)[1] = make_float4(x1, y1, z1, w1f);
        }
    }

    // ---- grid barrier over all 160 blocks ----
    __syncthreads();
    if (tid == 0) {
        __threadfence();
        unsigned ph = *(volatile unsigned*)&g_bar_phase;
        __threadfence();
        if (atomicAdd(&g_bar_count, 1u) == NEPI - 1u) {
            *(volatile unsigned*)&g_bar_count = 0u;
            __threadfence();
            atomicAdd(&g_bar_phase, 1u);          // release
        } else {
            while (*(volatile unsigned*)&g_bar_phase == ph) __nanosleep(64);
        }
        __threadfence();
    }
    __syncthreads();

    // ---- Phase F: k-reduce + bias + relu + cls dot; atomicAdd into out ----
    // 160 blocks x 128 thr = 640 warps = 64 b x 10 warps; warp owns 32 d4.
    {
        const int g    = bid * 128 + tid;
        const int w    = g >> 5;                  // warp 0..639
        const int lane = g & 31;
        const int b    = w / 10;                  // 0..63
        const int d4   = (w % 10) * 32 + lane;    // 0..319
        const float4* xp = reinterpret_cast<const float4*>(g_xpart);

        float4 s = reinterpret_cast<const float4*>(dense_b)[d4];
#pragma unroll
        for (int ks = 0; ks < KS; ++ks) {
            float4 v = xp[((size_t)ks * Bq + b) * D4 + d4];
            s.x += v.x; s.y += v.y; s.z += v.z; s.w += v.w;
        }
        s.x = fmaxf(s.x, 0.f); s.y = fmaxf(s.y, 0.f);
        s.z = fmaxf(s.z, 0.f); s.w = fmaxf(s.w, 0.f);

        float4 cw = reinterpret_cast<const float4*>(cls_w)[d4];
        float part = s.x * cw.x + s.y * cw.y + s.z * cw.z + s.w * cw.w;

#pragma unroll
        for (int o = 16; o > 0; o >>= 1)
            part += __shfl_down_sync(0xffffffffu, part, o);
        if (lane == 0)
            atomicAdd(&out[b], part);             // 10 adds per b total
    }
}

// ---------------------------------------------------------------------------
extern "C" void kernel_launch(void* const* d_in, const int* in_sizes, int n_in,
                              void* d_out, int out_size)
{
    const float* prev    = (const float*)d_in[0];
    const int*   lengths = (const int*)  d_in[1];
    const float* dense_w = (const float*)d_in[2];
    const float* dense_b = (const float*)d_in[3];
    const float* cls_w   = (const float*)d_in[4];
    const float* cls_b   = (const float*)d_in[5];
    float*       out     = (float*)d_out;

    pool_kernel    <<<GPOOL, D4>>>(prev, lengths);
    epilogue_kernel<<<NEPI, 128>>>(dense_w, dense_b, cls_w, cls_b, out);
}

// round 16
// speedup vs baseline: 1.0123x; 1.0123x over previous
#include <cuda_runtime.h>
#include <cuda_bf16.h>

// Problem: B=64, L=1024, D=1280
//   pool_len = lengths + 2
//   emb[b,d]  = mean over l < pool_len of prev[b,l,d]
//   x         = relu(emb @ dense_w + dense_b)        [64,1280]
//   out       = x @ cls_w + cls_b                    [64,1]
//
// Three launches:
//  1) pool_kernel : 592 blocks x 320 thr (R11 config, proven best). Exact
//     task list over valid 64-row segments; last block per b reduces and
//     writes embT. Each block ALSO prefetches an 11 KB slice of dense_w into
//     L2 (evict_last) so the gemm kernel reads W from L2, not cold DRAM.
//  2) gemm_kernel : 320 blocks x 256 thr, KS=8 k-split FFMA2 (R12, proven).
//  3) final_kernel: grid(64,5) x 64 thr, k-reduce + bias + relu + cls dot,
//     atomicAdd (R12, proven; out init'd by gemm block 0).

#define Bq     64
#define Lq     1024
#define Dq     1280
#define D4     320           // float4 per row
#define SEGR   64            // rows per pool segment
#define MAXSEG 16
#define GPOOL  592           // pool blocks

#define KS     8             // GEMM k-splits
#define KCH    160           // k per split
#define KC     80            // k staged per chunk
#define NJ     40            // j tiles
#define JTW    32            // j tile width

#define WLINES ((Dq * Dq * 4) / 128)             // 51200 128B lines of W
#define LPB    ((WLINES + GPOOL - 1) / GPOOL)    // 87 lines per pool block

typedef unsigned long long u64;

// scratch (allocation-free: __device__ globals)
__device__ float    g_part [Bq * MAXSEG * Dq];  // pool partials (5.24 MB)
__device__ float    g_embT [Dq * Bq];           // emb transposed [k][b]
__device__ float    g_xpart[KS * Bq * Dq];      // GEMM k-partials (2.62 MB)
__device__ unsigned g_cnt  [Bq];                // pool arrival counters

// packed f32x2 FMA (SASS FFMA2)
__device__ __forceinline__ u64 ffma2(u64 a, u64 b, u64 c) {
    u64 d;
    asm("fma.rn.f32x2 %0, %1, %2, %3;" : "=l"(d) : "l"(a), "l"(b), "l"(c));
    return d;
}
__device__ __forceinline__ u64 pack2(float lo, float hi) {
    u64 d;
    asm("mov.b64 %0, {%1, %2};" : "=l"(d) : "f"(lo), "f"(hi));
    return d;
}
__device__ __forceinline__ void unpack2(u64 v, float& lo, float& hi) {
    asm("mov.b64 {%0, %1}, %2;" : "=f"(lo), "=f"(hi) : "l"(v));
}

// ---------------------------------------------------------------------------
// Kernel 1: balanced ragged pool + fused per-b reduction + W L2 prefetch.
// ---------------------------------------------------------------------------
__global__ void __launch_bounds__(D4) pool_kernel(
    const float* __restrict__ prev, const int* __restrict__ lengths,
    const float* __restrict__ W)
{
    __shared__ int s_pre[Bq + 1];
    __shared__ int s_last;

    const int tid = threadIdx.x;
    const int bid = blockIdx.x;

    if (tid == 0) {
        int acc = 0;
        s_pre[0] = 0;
        for (int b = 0; b < Bq; ++b) {
            int pl = lengths[b] + 2;
            acc += (pl + SEGR - 1) >> 6;          // ceil(pl/64)
            s_pre[b + 1] = acc;
        }
    }
    __syncthreads();
    const int S = s_pre[Bq];                      // total valid segments

    for (int t = bid; t < S; t += GPOOL) {
        // binary search: b with s_pre[b] <= t < s_pre[b+1]
        int lo = 0, hi = Bq;
        while (hi - lo > 1) {
            int m = (lo + hi) >> 1;
            if (s_pre[m] <= t) lo = m; else hi = m;
        }
        const int b    = lo;
        const int seg  = t - s_pre[b];
        const int pl   = lengths[b] + 2;
        const int l0   = seg * SEGR;
        const int n    = min(SEGR, pl - l0);      // >= 1 by construction
        const int nseg = s_pre[b + 1] - s_pre[b];

        float4 a0 = make_float4(0.f, 0.f, 0.f, 0.f);
        float4 a1 = a0, a2 = a0, a3 = a0;

        const float4* __restrict__ p =
            reinterpret_cast<const float4*>(prev) + ((size_t)b * Lq + l0) * D4 + tid;
        int l = 0;
        for (; l + 8 <= n; l += 8) {
            float4 v0 = p[(size_t)(l + 0) * D4];
            float4 v1 = p[(size_t)(l + 1) * D4];
            float4 v2 = p[(size_t)(l + 2) * D4];
            float4 v3 = p[(size_t)(l + 3) * D4];
            float4 v4 = p[(size_t)(l + 4) * D4];
            float4 v5 = p[(size_t)(l + 5) * D4];
            float4 v6 = p[(size_t)(l + 6) * D4];
            float4 v7 = p[(size_t)(l + 7) * D4];
            a0.x += v0.x; a0.y += v0.y; a0.z += v0.z; a0.w += v0.w;
            a1.x += v1.x; a1.y += v1.y; a1.z += v1.z; a1.w += v1.w;
            a2.x += v2.x; a2.y += v2.y; a2.z += v2.z; a2.w += v2.w;
            a3.x += v3.x; a3.y += v3.y; a3.z += v3.z; a3.w += v3.w;
            a0.x += v4.x; a0.y += v4.y; a0.z += v4.z; a0.w += v4.w;
            a1.x += v5.x; a1.y += v5.y; a1.z += v5.z; a1.w += v5.w;
            a2.x += v6.x; a2.y += v6.y; a2.z += v6.z; a2.w += v6.w;
            a3.x += v7.x; a3.y += v7.y; a3.z += v7.z; a3.w += v7.w;
        }
        for (; l < n; ++l) {
            float4 v = p[(size_t)l * D4];
            a0.x += v.x; a0.y += v.y; a0.z += v.z; a0.w += v.w;
        }
        float4 s;
        s.x = (a0.x + a1.x) + (a2.x + a3.x);
        s.y = (a0.y + a1.y) + (a2.y + a3.y);
        s.z = (a0.z + a1.z) + (a2.z + a3.z);
        s.w = (a0.w + a1.w) + (a2.w + a3.w);
        reinterpret_cast<float4*>(g_part)[((size_t)b * MAXSEG + seg) * D4 + tid] = s;

        // publish partial, count arrival; last arrival reduces this b
        __threadfence();
        __syncthreads();
        if (tid == 0) {
            unsigned old = atomicAdd(&g_cnt[b], 1u);
            s_last = (((old + 1u) % (unsigned)nseg) == 0u) ? 1 : 0;
        }
        __syncthreads();
        if (s_last) {
            __threadfence();   // acquire other blocks' partials
            const float4* gp = reinterpret_cast<const float4*>(g_part)
                               + (size_t)b * MAXSEG * D4 + tid;
            float4 r = make_float4(0.f, 0.f, 0.f, 0.f);
            for (int sg = 0; sg < nseg; ++sg) {
                float4 v = gp[(size_t)sg * D4];
                r.x += v.x; r.y += v.y; r.z += v.z; r.w += v.w;
            }
            const float inv = 1.0f / (float)pl;
            r.x *= inv; r.y *= inv; r.z *= inv; r.w *= inv;
            g_embT[(size_t)(4 * tid + 0) * Bq + b] = r.x;
            g_embT[(size_t)(4 * tid + 1) * Bq + b] = r.y;
            g_embT[(size_t)(4 * tid + 2) * Bq + b] = r.z;
            g_embT[(size_t)(4 * tid + 3) * Bq + b] = r.w;
        }
        __syncthreads();       // protect s_last across task iterations
    }

    // ---- prefetch this block's slice of dense_w into L2 (evict_last) ----
    // so gemm_kernel reads W from L2 instead of cold DRAM.
    {
        const char* wb = reinterpret_cast<const char*>(W);
        int line = bid * LPB + tid;
        if (tid < LPB && line < WLINES) {
            asm volatile("prefetch.global.L2::evict_last [%0];"
                         :: "l"(wb + (size_t)line * 128));
        }
    }
}

// ---------------------------------------------------------------------------
// Kernel 2: k-split GEMM (KS=8), FFMA2. grid 320 = ky*NJ + jx, 256 threads.
// Block tile 64b x 32j x 160k; thread 2b x 4j. Block 0 inits out[b] = cls_b.
// (R12 kernel, measured correct twice.)
// ---------------------------------------------------------------------------
__global__ void __launch_bounds__(256) gemm_kernel(
    const float* __restrict__ W, const float* __restrict__ cls_b,
    float* __restrict__ out)
{
    __shared__ __align__(16) float sE[KC][Bq];    // 20 KB
    __shared__ __align__(16) float sW[KC][JTW];   // 10 KB

    const int tid = threadIdx.x;
    const int ky  = blockIdx.x / NJ;              // 0..7
    const int jx  = blockIdx.x % NJ;              // 0..39
    const int k0  = ky * KCH;
    const int j0  = jx * JTW;
    const int bg  = tid >> 3;                     // 0..31 -> b = 2bg, 2bg+1
    const int jg  = tid & 7;                      // 0..7  -> j = 4jg..4jg+3

    if (blockIdx.x == 0 && tid < Bq)              // init out for final's atomics
        out[tid] = cls_b[0];

    u64 a00 = 0ull, a01 = 0ull, a10 = 0ull, a11 = 0ull;

    for (int c = 0; c < KCH; c += KC) {
        __syncthreads();
        for (int i = tid; i < KC * Bq; i += 256) {
            int kk = i >> 6;
            int bb = i & 63;
            sE[kk][bb] = g_embT[(size_t)(k0 + c + kk) * Bq + bb];
        }
        for (int i = tid; i < KC * JTW; i += 256) {
            int kk = i >> 5;
            int jj = i & 31;
            sW[kk][jj] = W[(size_t)(k0 + c + kk) * Dq + j0 + jj];
        }
        __syncthreads();

#pragma unroll 10
        for (int kk = 0; kk < KC; ++kk) {
            float2 e  = *reinterpret_cast<const float2*>(&sE[kk][2 * bg]);
            float4 w  = *reinterpret_cast<const float4*>(&sW[kk][4 * jg]);
            u64 e0  = pack2(e.x, e.x);
            u64 e1  = pack2(e.y, e.y);
            u64 w01 = pack2(w.x, w.y);
            u64 w23 = pack2(w.z, w.w);
            a00 = ffma2(e0, w01, a00);
            a01 = ffma2(e0, w23, a01);
            a10 = ffma2(e1, w01, a10);
            a11 = ffma2(e1, w23, a11);
        }
    }

    float x0, y0, z0, w0f, x1, y1, z1, w1f;
    unpack2(a00, x0, y0); unpack2(a01, z0, w0f);
    unpack2(a10, x1, y1); unpack2(a11, z1, w1f);
    const int b0 = 2 * bg;
    float* dst0 = &g_xpart[((size_t)ky * Bq + b0) * Dq + j0 + 4 * jg];
    *reinterpret_cast<float4*>(dst0)      = make_float4(x0, y0, z0, w0f);
    *reinterpret_cast<float4*>(dst0 + Dq) = make_float4(x1, y1, z1, w1f);
}

// ---------------------------------------------------------------------------
// Kernel 3: reduce k-partials, +bias, relu, dot cls_w, atomicAdd.
// grid(64, 5), 64 threads. (R12 kernel, measured correct twice.)
// ---------------------------------------------------------------------------
__global__ void __launch_bounds__(64) final_kernel(
    const float* __restrict__ dense_b,
    const float* __restrict__ cls_w,
    float* __restrict__ out)
{
    const int b   = blockIdx.x;
    const int tid = threadIdx.x;
    const int d4  = blockIdx.y * 64 + tid;        // 0..319
    const float4* xp = reinterpret_cast<const float4*>(g_xpart);

    float4 s = reinterpret_cast<const float4*>(dense_b)[d4];
#pragma unroll
    for (int ks = 0; ks < KS; ++ks) {
        float4 v = xp[((size_t)ks * Bq + b) * D4 + d4];
        s.x += v.x; s.y += v.y; s.z += v.z; s.w += v.w;
    }
    s.x = fmaxf(s.x, 0.f); s.y = fmaxf(s.y, 0.f);
    s.z = fmaxf(s.z, 0.f); s.w = fmaxf(s.w, 0.f);

    float4 w = reinterpret_cast<const float4*>(cls_w)[d4];
    float part = s.x * w.x + s.y * w.y + s.z * w.z + s.w * w.w;

#pragma unroll
    for (int o = 16; o > 0; o >>= 1)
        part += __shfl_down_sync(0xffffffffu, part, o);
    if ((tid & 31) == 0)
        atomicAdd(&out[b], part);                 // 10 adds per b total
}

// ---------------------------------------------------------------------------
extern "C" void kernel_launch(void* const* d_in, const int* in_sizes, int n_in,
                              void* d_out, int out_size)
{
    const float* prev    = (const float*)d_in[0];
    const int*   lengths = (const int*)  d_in[1];
    const float* dense_w = (const float*)d_in[2];
    const float* dense_b = (const float*)d_in[3];
    const float* cls_w   = (const float*)d_in[4];
    const float* cls_b   = (const float*)d_in[5];
    float*       out     = (float*)d_out;

    pool_kernel <<<GPOOL, D4>>>(prev, lengths, dense_w);
    gemm_kernel <<<KS * NJ, 256>>>(dense_w, cls_b, out);
    final_kernel<<<dim3(Bq, 5), 64>>>(dense_b, cls_w, out);
}